// round 1
// baseline (speedup 1.0000x reference)
#include <cuda_runtime.h>
#include <math.h>

#define BB    64
#define PP    196
#define EE    2048
#define HH    512
#define EMBD  512
#define VSZ   10000
#define TCAP  50
#define TMAXX 49
#define BPP   (BB*PP)          // 12544
#define G3    1536             // 3*H
#define KIH   (EE+EMBD)        // 2560

#define PRED_SZ   ((size_t)BB*TCAP*VSZ)          // 32,000,000
#define ALPHA_OFF PRED_SZ
#define ALPHA_SZ  ((size_t)BB*TCAP*PP)           // 627,200
#define DEC_OFF   (ALPHA_OFF + ALPHA_SZ)

// ---------------- scratch (static device allocations only) ----------------
__device__ float g_xwx[(size_t)BPP*EE];   // 102.8 MB precomputed attention projections
__device__ float g_fm  [BB*EE];
__device__ float g_h   [BB*HH];
__device__ float g_hwh [BB*EE];
__device__ float g_gate[BB*EE];
__device__ float g_lam [BB*PP];
__device__ float g_alpha[BB*PP];
__device__ float g_inp [BB*KIH];
__device__ float g_gi  [BB*G3];
__device__ float g_gh  [BB*G3];
__device__ int   g_dec [BB];
__device__ float g_part[157*8*64*64];     // split-K partials (max 157 tiles x 8 splits)
__device__ unsigned int g_cnt[157];       // zero-init; finishers reset to 0

// ---------------- helpers ----------------
__device__ __forceinline__ float sigf(float x){ return 1.f/(1.f+expf(-x)); }

// ---------------- dec + output tail ----------------
__global__ void dec_kernel(const int* __restrict__ lengths, float* __restrict__ outp){
    int b = threadIdx.x;
    if (b < BB){
        int d = lengths[b] - 1;
        g_dec[b] = d;
        outp[DEC_OFF + b] = (float)d;
    }
}

// ---------------- mean over P ----------------
__global__ __launch_bounds__(256) void mean_kernel(const float* __restrict__ feat){
    int b = blockIdx.y;
    int e = blockIdx.x*256 + threadIdx.x;
    const float* f = feat + (size_t)b*PP*EE + e;
    float s = 0.f;
    #pragma unroll 4
    for (int p = 0; p < PP; p++) s += f[(size_t)p*EE];
    g_fm[b*EE + e] = s * (1.f/(float)PP);
}

// ---------------- big SGEMM: x_wx = features @ Wx_w^T + Wx_b ----------------
// C[m][n], m in [0,12544), n in [0,2048). 128x128 tile, BK=8, 8x8 per thread.
__global__ __launch_bounds__(256) void xwx_gemm(const float* __restrict__ A,
                                                const float* __restrict__ W,
                                                const float* __restrict__ bias){
    __shared__ __align__(16) float As[8][128];
    __shared__ __align__(16) float Bs[8][128];
    int tid = threadIdx.x;
    int m0 = blockIdx.y*128, n0 = blockIdx.x*128;
    int lr = tid >> 1;            // 0..127
    int lk = (tid & 1) * 4;       // 0 or 4
    int ty = tid >> 4, tx = tid & 15;
    float acc[8][8];
    #pragma unroll
    for (int i=0;i<8;i++)
        #pragma unroll
        for (int j=0;j<8;j++) acc[i][j]=0.f;

    const float* Ap = A + (size_t)(m0+lr)*EE + lk;
    const float* Wp = W + (size_t)(n0+lr)*EE + lk;

    for (int k0 = 0; k0 < EE; k0 += 8){
        float4 av = *(const float4*)(Ap + k0);
        float4 wv = *(const float4*)(Wp + k0);
        As[lk+0][lr]=av.x; As[lk+1][lr]=av.y; As[lk+2][lr]=av.z; As[lk+3][lr]=av.w;
        Bs[lk+0][lr]=wv.x; Bs[lk+1][lr]=wv.y; Bs[lk+2][lr]=wv.z; Bs[lk+3][lr]=wv.w;
        __syncthreads();
        #pragma unroll
        for (int kk = 0; kk < 8; kk++){
            float a[8], w[8];
            *(float4*)&a[0] = *(const float4*)&As[kk][ty*8];
            *(float4*)&a[4] = *(const float4*)&As[kk][ty*8+4];
            *(float4*)&w[0] = *(const float4*)&Bs[kk][tx*8];
            *(float4*)&w[4] = *(const float4*)&Bs[kk][tx*8+4];
            #pragma unroll
            for (int i=0;i<8;i++)
                #pragma unroll
                for (int j=0;j<8;j++) acc[i][j] = fmaf(a[i], w[j], acc[i][j]);
        }
        __syncthreads();
    }
    #pragma unroll
    for (int i=0;i<8;i++){
        int m = m0 + ty*8 + i;
        #pragma unroll
        for (int j=0;j<8;j++){
            int n = n0 + tx*8 + j;
            g_xwx[(size_t)m*EE + n] = acc[i][j] + bias[n];
        }
    }
}

// ---------------- generic skinny GEMM: C(64xN) = A(64xK) @ W(NxK)^T + bias ----------------
// split-K across gridDim.z, deterministic last-block finisher reduction.
// a_id: 0=g_fm 1=g_h 2=g_inp ; c_id: 0=g_h 1=g_hwh 2=g_gate 3=g_gi 4=g_gh
// act: 0 none, 1 sigmoid ; mode: 0 store C[r*N+n], 1 masked pred store into outp
__global__ __launch_bounds__(256) void sgemm64(int a_id, int lda,
                                               const float* __restrict__ W,
                                               const float* __restrict__ bias,
                                               int c_id, int N, int Ktot,
                                               int act, int mode,
                                               float* __restrict__ outp, int t){
    const float* A = (a_id==0) ? g_fm : (a_id==1) ? g_h : g_inp;
    float* Cptr = (c_id==0) ? g_h : (c_id==1) ? g_hwh : (c_id==2) ? g_gate
                 : (c_id==3) ? g_gi : g_gh;

    __shared__ __align__(16) float As[16][68];
    __shared__ __align__(16) float Ws[16][68];
    __shared__ unsigned int s_last;

    int tid = threadIdx.x;
    int n0 = blockIdx.x * 64;
    int ksplit = gridDim.z;
    int kchunk = Ktot / ksplit;
    int kbeg = blockIdx.z * kchunk;
    int kend = kbeg + kchunk;
    int lr = tid >> 2;            // 0..63
    int lk = (tid & 3) << 2;      // 0,4,8,12
    int ty = tid >> 4, tx = tid & 15;

    float acc[4][4];
    #pragma unroll
    for (int i=0;i<4;i++)
        #pragma unroll
        for (int j=0;j<4;j++) acc[i][j]=0.f;

    int wr = n0 + lr;
    for (int k0 = kbeg; k0 < kend; k0 += 16){
        float4 av = *(const float4*)(A + (size_t)lr*lda + k0 + lk);
        float4 wv = make_float4(0.f,0.f,0.f,0.f);
        if (wr < N) wv = *(const float4*)(W + (size_t)wr*Ktot + k0 + lk);
        As[lk+0][lr]=av.x; As[lk+1][lr]=av.y; As[lk+2][lr]=av.z; As[lk+3][lr]=av.w;
        Ws[lk+0][lr]=wv.x; Ws[lk+1][lr]=wv.y; Ws[lk+2][lr]=wv.z; Ws[lk+3][lr]=wv.w;
        __syncthreads();
        #pragma unroll
        for (int kk = 0; kk < 16; kk++){
            float4 a4 = *(const float4*)&As[kk][ty*4];
            float4 w4 = *(const float4*)&Ws[kk][tx*4];
            float a[4] = {a4.x,a4.y,a4.z,a4.w};
            float w[4] = {w4.x,w4.y,w4.z,w4.w};
            #pragma unroll
            for (int i=0;i<4;i++)
                #pragma unroll
                for (int j=0;j<4;j++) acc[i][j] = fmaf(a[i], w[j], acc[i][j]);
        }
        __syncthreads();
    }

    if (ksplit > 1){
        float* pp = &g_part[((size_t)blockIdx.x*8 + blockIdx.z)*4096];
        #pragma unroll
        for (int i=0;i<4;i++)
            #pragma unroll
            for (int j=0;j<4;j++) pp[(ty*4+i)*64 + tx*4+j] = acc[i][j];
        __threadfence();
        __syncthreads();
        if (tid == 0){
            unsigned int v = atomicAdd(&g_cnt[blockIdx.x], 1u);
            s_last = (v == (unsigned)(ksplit - 1)) ? 1u : 0u;
        }
        __syncthreads();
        if (!s_last) return;
        __threadfence();
        #pragma unroll
        for (int i=0;i<4;i++)
            #pragma unroll
            for (int j=0;j<4;j++){
                float v = 0.f;
                for (int kz = 0; kz < ksplit; kz++)
                    v += g_part[((size_t)blockIdx.x*8 + kz)*4096 + (ty*4+i)*64 + tx*4+j];
                acc[i][j] = v;
            }
        __syncthreads();
        if (tid == 0) g_cnt[blockIdx.x] = 0;   // reset for next launch
    }

    #pragma unroll
    for (int i=0;i<4;i++){
        int r = ty*4 + i;
        #pragma unroll
        for (int j=0;j<4;j++){
            int n = n0 + tx*4 + j;
            if (n < N){
                float v = acc[i][j] + bias[n];
                if (act == 1) v = sigf(v);
                if (mode == 0){
                    Cptr[(size_t)r*N + n] = v;
                } else {
                    if (g_dec[r] >= t)
                        outp[(size_t)r*TCAP*VSZ + (size_t)t*VSZ + n] = v;
                }
            }
        }
    }
}

// ---------------- attention logits: lam[b,p] = sum_e tanh(xwx+hwh)*Vw + Vb ----------------
__global__ __launch_bounds__(256) void att_kernel(const float* __restrict__ Vw,
                                                  const float* __restrict__ Vb){
    int b = blockIdx.y, p = blockIdx.x;
    const float4* x = (const float4*)(g_xwx + (size_t)(b*PP + p)*EE);
    const float4* h = (const float4*)(g_hwh + (size_t)b*EE);
    const float4* v = (const float4*)Vw;
    float s = 0.f;
    #pragma unroll 2
    for (int i = threadIdx.x; i < EE/4; i += 256){
        float4 xv = x[i], hv = h[i], vv = v[i];
        s += tanhf(xv.x+hv.x)*vv.x;
        s += tanhf(xv.y+hv.y)*vv.y;
        s += tanhf(xv.z+hv.z)*vv.z;
        s += tanhf(xv.w+hv.w)*vv.w;
    }
    #pragma unroll
    for (int o = 16; o > 0; o >>= 1) s += __shfl_xor_sync(0xffffffffu, s, o);
    __shared__ float sh[8];
    if ((threadIdx.x & 31) == 0) sh[threadIdx.x >> 5] = s;
    __syncthreads();
    if (threadIdx.x == 0){
        float tt = 0.f;
        #pragma unroll
        for (int w2 = 0; w2 < 8; w2++) tt += sh[w2];
        g_lam[b*PP + p] = tt + Vb[0];
    }
}

// ---------------- softmax over P + masked alpha output ----------------
__global__ __launch_bounds__(256) void softmax_kernel(float* __restrict__ outp, int t){
    int b = blockIdx.x, tid = threadIdx.x;
    __shared__ float sh[256];
    float v = (tid < PP) ? g_lam[b*PP + tid] : -1e30f;
    sh[tid] = v; __syncthreads();
    for (int s = 128; s > 0; s >>= 1){ if (tid < s) sh[tid] = fmaxf(sh[tid], sh[tid+s]); __syncthreads(); }
    float mx = sh[0]; __syncthreads();
    float e = (tid < PP) ? expf(v - mx) : 0.f;
    sh[tid] = e; __syncthreads();
    for (int s = 128; s > 0; s >>= 1){ if (tid < s) sh[tid] += sh[tid+s]; __syncthreads(); }
    float inv = 1.f / sh[0];
    if (tid < PP){
        float a = e * inv;
        g_alpha[b*PP + tid] = a;
        if (g_dec[b] >= t)
            outp[ALPHA_OFF + (size_t)b*TCAP*PP + (size_t)t*PP + tid] = a;
    }
}

// ---------------- z = sum_p alpha*features, gated; plus embedding concat ----------------
__global__ __launch_bounds__(256) void zbuild_kernel(const float* __restrict__ feat,
                                                     const int* __restrict__ caps,
                                                     const float* __restrict__ embw,
                                                     int t){
    int b = blockIdx.y;
    int e = blockIdx.x*256 + threadIdx.x;     // 0..2559
    if (e < EE){
        const float* arow = g_alpha + b*PP;
        const float* f = feat + (size_t)b*PP*EE + e;
        float s = 0.f;
        #pragma unroll 4
        for (int p = 0; p < PP; p++) s = fmaf(arow[p], f[(size_t)p*EE], s);
        g_inp[b*KIH + e] = g_gate[b*EE + e] * s;
    } else {
        int j = e - EE;
        int tok = caps[b*TCAP + t];
        g_inp[b*KIH + e] = embw[(size_t)tok*EMBD + j];
    }
}

// ---------------- GRU combine + masked h update ----------------
__global__ __launch_bounds__(256) void gru_combine(int t){
    int idx = blockIdx.x*256 + threadIdx.x;   // 0..32767
    int b = idx >> 9, j = idx & 511;
    float ir = g_gi[b*G3 + j],       hr = g_gh[b*G3 + j];
    float iz = g_gi[b*G3 + 512 + j], hz = g_gh[b*G3 + 512 + j];
    float in_= g_gi[b*G3 + 1024 + j],hn = g_gh[b*G3 + 1024 + j];
    float h  = g_h[b*HH + j];
    float r  = sigf(ir + hr);
    float z  = sigf(iz + hz);
    float n  = tanhf(in_ + r*hn);
    float hnew = (1.f - z)*n + z*h;
    if (g_dec[b] >= t) g_h[b*HH + j] = hnew;
}

// ---------------- launch ----------------
extern "C" void kernel_launch(void* const* d_in, const int* in_sizes, int n_in,
                              void* d_out, int out_size){
    const float* features = (const float*)d_in[0];
    const int*   captions = (const int*)  d_in[1];
    const int*   lengths  = (const int*)  d_in[2];
    const float* Wx_w  = (const float*)d_in[3];
    const float* Wx_b  = (const float*)d_in[4];
    const float* Wh_w  = (const float*)d_in[5];
    const float* Wh_b  = (const float*)d_in[6];
    const float* V_w   = (const float*)d_in[7];
    const float* V_b   = (const float*)d_in[8];
    const float* ih_w  = (const float*)d_in[9];   // init_h_w
    const float* ih_b  = (const float*)d_in[10];
    const float* fb_w  = (const float*)d_in[11];  // f_beta_w
    const float* fb_b  = (const float*)d_in[12];
    const float* emb_w = (const float*)d_in[13];
    const float* gih_w = (const float*)d_in[14];
    const float* gih_b = (const float*)d_in[15];
    const float* ghh_w = (const float*)d_in[16];
    const float* ghh_b = (const float*)d_in[17];
    const float* fc1_w = (const float*)d_in[18];
    const float* fc1_b = (const float*)d_in[19];
    float* out = (float*)d_out;

    cudaMemsetAsync(d_out, 0, (size_t)out_size * sizeof(float), 0);
    dec_kernel<<<1, 64>>>(lengths, out);
    mean_kernel<<<dim3(EE/256, BB), 256>>>(features);
    // h0 = fm @ init_h_w^T + b : N=512, K=2048, split-K 4
    sgemm64<<<dim3(HH/64, 1, 4), 256>>>(0, EE, ih_w, ih_b, 0, HH, EE, 0, 0, out, 0);
    // x_wx = features @ Wx_w^T + b
    xwx_gemm<<<dim3(EE/128, BPP/128), 256>>>(features, Wx_w, Wx_b);

    for (int t = 0; t < TMAXX; t++){
        // h_wh (N=2048,K=512) and gate (sigmoid)
        sgemm64<<<dim3(EE/64, 1, 2), 256>>>(1, HH, Wh_w, Wh_b, 1, EE, HH, 0, 0, out, t);
        sgemm64<<<dim3(EE/64, 1, 2), 256>>>(1, HH, fb_w, fb_b, 2, EE, HH, 1, 0, out, t);
        att_kernel<<<dim3(PP, BB), 256>>>(V_w, V_b);
        softmax_kernel<<<BB, 256>>>(out, t);
        zbuild_kernel<<<dim3(KIH/256, BB), 256>>>(features, captions, emb_w, t);
        // GRU input-hidden (N=1536,K=2560, split 8) and hidden-hidden (K=512, split 2)
        sgemm64<<<dim3(G3/64, 1, 8), 256>>>(2, KIH, gih_w, gih_b, 3, G3, KIH, 0, 0, out, t);
        sgemm64<<<dim3(G3/64, 1, 2), 256>>>(1, HH, ghh_w, ghh_b, 4, G3, HH, 0, 0, out, t);
        gru_combine<<<(BB*HH)/256, 256>>>(t);
        // fc1: N=10000, K=512, masked store directly into preds
        sgemm64<<<dim3(157, 1, 2), 256>>>(1, HH, fc1_w, fc1_b, 0, VSZ, HH, 0, 1, out, t);
    }
}